// round 13
// baseline (speedup 1.0000x reference)
#include <cuda_runtime.h>
#include <math.h>

typedef unsigned long long u64;
#define S 2048
#define TK 16
#define SCAP 128

__device__ float g_h[4096*512];
__device__ float g_xcol[4096*448];
__device__ float g_W7[512*448];
__device__ float g_Q[32768*64];
__device__ float g_K[32768*64];
__device__ float g_V[32768*64];
__device__ float g_Kp[32768*64];
__device__ float g_Vp[32768*64];
__device__ float g_gs[32768*2048];
__device__ float g_tw[32768*16];
__device__ int   g_tix[32768*16];
__device__ float g_attn[4096*512];
__device__ float g_sp[4096*512];
__device__ float g_res[4096*512];

__device__ __forceinline__ void fma2(u64& d, u64 a, u64 b) {
    asm("fma.rn.f32x2 %0, %1, %2, %0;" : "+l"(d) : "l"(a), "l"(b));
}
__device__ __forceinline__ float2 unpk(u64 v) {
    unsigned lo, hi;
    asm("mov.b64 {%0, %1}, %2;" : "=r"(lo), "=r"(hi) : "l"(v));
    return make_float2(__uint_as_float(lo), __uint_as_float(hi));
}

// A stored DUPLICATED (row m at cols 2m,2m+1), B natural.
// acc[8][4]: 8 m-rows x 4 n-pairs.
#define STORE_TILE(b) do { \
    *(float2*)&As[b][lcg*4+0][lrow*2] = make_float2(sa0.x, sa0.x); \
    *(float2*)&As[b][lcg*4+1][lrow*2] = make_float2(sa0.y, sa0.y); \
    *(float2*)&As[b][lcg*4+2][lrow*2] = make_float2(sa0.z, sa0.z); \
    *(float2*)&As[b][lcg*4+3][lrow*2] = make_float2(sa0.w, sa0.w); \
    *(float2*)&As[b][lcg*4+0][lrow*2+128] = make_float2(sa1.x, sa1.x); \
    *(float2*)&As[b][lcg*4+1][lrow*2+128] = make_float2(sa1.y, sa1.y); \
    *(float2*)&As[b][lcg*4+2][lrow*2+128] = make_float2(sa1.z, sa1.z); \
    *(float2*)&As[b][lcg*4+3][lrow*2+128] = make_float2(sa1.w, sa1.w); \
    Bs[b][lcg*4+0][lrow] = sw0.x; Bs[b][lcg*4+1][lrow] = sw0.y; \
    Bs[b][lcg*4+2][lrow] = sw0.z; Bs[b][lcg*4+3][lrow] = sw0.w; \
    Bs[b][lcg*4+0][lrow+64] = sw1.x; Bs[b][lcg*4+1][lrow+64] = sw1.y; \
    Bs[b][lcg*4+2][lrow+64] = sw1.z; Bs[b][lcg*4+3][lrow+64] = sw1.w; \
} while (0)

#define COMPUTE_TILE(b) do { \
    _Pragma("unroll") \
    for (int kk = 0; kk < 16; kk++) { \
        const float* Ar = As[b][kk]; \
        const float* Br = Bs[b][kk]; \
        u64 ad[8]; \
        ad[0] = *(const u64*)(Ar + ty*8); \
        ad[1] = *(const u64*)(Ar + ty*8 + 2); \
        ad[2] = *(const u64*)(Ar + ty*8 + 4); \
        ad[3] = *(const u64*)(Ar + ty*8 + 6); \
        ad[4] = *(const u64*)(Ar + 128 + ty*8); \
        ad[5] = *(const u64*)(Ar + 128 + ty*8 + 2); \
        ad[6] = *(const u64*)(Ar + 128 + ty*8 + 4); \
        ad[7] = *(const u64*)(Ar + 128 + ty*8 + 6); \
        u64 bd[4]; \
        bd[0] = *(const u64*)(Br + tx*4); \
        bd[1] = *(const u64*)(Br + tx*4 + 2); \
        bd[2] = *(const u64*)(Br + 64 + tx*4); \
        bd[3] = *(const u64*)(Br + 64 + tx*4 + 2); \
        _Pragma("unroll") \
        for (int im = 0; im < 8; im++) \
            _Pragma("unroll") \
            for (int jn = 0; jn < 4; jn++) \
                fma2(acc[im][jn], ad[im], bd[jn]); \
    } \
} while (0)

// m-row and n-col helpers for the epilogues
#define MROW(im) (((im) < 4) ? (ty*4 + (im)) : (64 + ty*4 + (im) - 4))
#define NCOL(jn) (((jn) < 2) ? (tx*4 + (jn)*2) : (64 + tx*4 + ((jn)-2)*2))

// ======================================== conv prep: im2col + padded W =====
__global__ __launch_bounds__(256) void xcol_kernel(const float* __restrict__ x) {
    int idx = blockIdx.x*256 + threadIdx.x;
    int s = idx / 112;
    int r = idx % 112;
    int t = r >> 4, icg = r & 15;
    int b = s >> 11, ss = s & 2047;
    int s_in = ss - 3 + t;
    float4 v = make_float4(0.f, 0.f, 0.f, 0.f);
    if (s_in >= 0 && s_in < S)
        v = *(const float4*)&x[((size_t)(b*S + s_in))*64 + icg*4];
    *(float4*)&g_xcol[(size_t)s*448 + t*64 + icg*4] = v;
}

__global__ __launch_bounds__(256) void wpad_kernel(
        const float* __restrict__ w1, const float* __restrict__ w2,
        const float* __restrict__ w3) {
    int idx = blockIdx.x*256 + threadIdx.x;
    int oc = idx / 448;
    int k  = idx % 448;
    int t = k >> 6, ic = k & 63;
    float val = 0.f;
    if (oc < 171) {
        int tt = t - 2;
        if (tt >= 0 && tt < 3) val = w1[(oc*64 + ic)*3 + tt];
    } else if (oc < 342) {
        int tt = t - 1, o = oc - 171;
        if (tt >= 0 && tt < 5) val = w2[(o*64 + ic)*5 + tt];
    } else {
        int o = oc - 342;
        val = w3[(o*64 + ic)*7 + t];
    }
    g_W7[(size_t)oc*448 + k] = val;
}

// ======================================== conv GEMM =========================
__global__ __launch_bounds__(256, 2) void conv_gemm_kernel(
        const float* __restrict__ b1, const float* __restrict__ b2,
        const float* __restrict__ b3) {
    __shared__ __align__(16) float As[2][16][264];
    __shared__ __align__(16) float Bs[2][16][132];
    int m0 = blockIdx.x * 128;
    int n0 = blockIdx.y * 128;
    int tid = threadIdx.x;
    int tx = tid & 15, ty = tid >> 4;
    int lrow = tid >> 2, lcg = tid & 3;
    u64 acc[8][4] = {};
    const float* Ap0 = &g_xcol[(size_t)(m0+lrow)*448    + lcg*4];
    const float* Ap1 = &g_xcol[(size_t)(m0+lrow+64)*448 + lcg*4];
    const float* Wp0 = &g_W7[(size_t)(n0+lrow)*448      + lcg*4];
    const float* Wp1 = &g_W7[(size_t)(n0+lrow+64)*448   + lcg*4];

    {
        float4 sa0 = *(const float4*)Ap0;
        float4 sa1 = *(const float4*)Ap1;
        float4 sw0 = *(const float4*)Wp0;
        float4 sw1 = *(const float4*)Wp1;
        STORE_TILE(0);
    }
    __syncthreads();

    #pragma unroll 1
    for (int kt = 0; kt < 28; kt++) {
        int cur = kt & 1;
        float4 sa0, sa1, sw0, sw1;
        if (kt < 27) {
            int k0 = (kt+1)*16;
            sa0 = *(const float4*)(Ap0 + k0);
            sa1 = *(const float4*)(Ap1 + k0);
            sw0 = *(const float4*)(Wp0 + k0);
            sw1 = *(const float4*)(Wp1 + k0);
        }
        COMPUTE_TILE(cur);
        if (kt < 27) STORE_TILE(cur ^ 1);
        __syncthreads();
    }
    #pragma unroll
    for (int im = 0; im < 8; im++) {
        int m = m0 + MROW(im);
        #pragma unroll
        for (int jn = 0; jn < 4; jn++) {
            int n = n0 + NCOL(jn);
            float2 v = unpk(acc[im][jn]);
            float bb0 = (n   < 171) ? b1[n]   : (n   < 342 ? b2[n-171]   : b3[n-342]);
            float bb1 = (n+1 < 171) ? b1[n+1] : (n+1 < 342 ? b2[n+1-171] : b3[n+1-342]);
            *(float2*)&g_h[(size_t)m*512 + n] =
                make_float2(fmaxf(v.x + bb0, 0.f), fmaxf(v.y + bb1, 0.f));
        }
    }
}

// ======================================== qkv GEMM ==========================
__global__ __launch_bounds__(256, 2) void qkv_kernel(
        const float* __restrict__ Wq, const float* __restrict__ bq,
        const float* __restrict__ Wk, const float* __restrict__ bk,
        const float* __restrict__ Wv, const float* __restrict__ bv) {
    __shared__ __align__(16) float As[2][16][264];
    __shared__ __align__(16) float Bs[2][16][132];
    int m0 = blockIdx.x * 128;
    int by = blockIdx.y;
    const float *W, *bias; float* dst;
    if (by < 4)      { W = Wq; bias = bq; dst = g_Q; }
    else if (by < 8) { W = Wk; bias = bk; dst = g_K; }
    else             { W = Wv; bias = bv; dst = g_V; }
    int n0 = (by & 3) * 128;

    int tid = threadIdx.x;
    int tx = tid & 15, ty = tid >> 4;
    int lrow = tid >> 2, lcg = tid & 3;
    u64 acc[8][4] = {};
    const float* Ap0 = &g_h[(size_t)(m0+lrow)*512    + lcg*4];
    const float* Ap1 = &g_h[(size_t)(m0+lrow+64)*512 + lcg*4];
    const float* Wp0 = &W[(size_t)(n0+lrow)*512      + lcg*4];
    const float* Wp1 = &W[(size_t)(n0+lrow+64)*512   + lcg*4];

    {
        float4 sa0 = *(const float4*)Ap0;
        float4 sa1 = *(const float4*)Ap1;
        float4 sw0 = *(const float4*)Wp0;
        float4 sw1 = *(const float4*)Wp1;
        STORE_TILE(0);
    }
    __syncthreads();

    #pragma unroll 1
    for (int kt = 0; kt < 32; kt++) {
        int cur = kt & 1;
        float4 sa0, sa1, sw0, sw1;
        if (kt < 31) {
            int k0 = (kt+1)*16;
            sa0 = *(const float4*)(Ap0 + k0);
            sa1 = *(const float4*)(Ap1 + k0);
            sw0 = *(const float4*)(Wp0 + k0);
            sw1 = *(const float4*)(Wp1 + k0);
        }
        COMPUTE_TILE(cur);
        if (kt < 31) STORE_TILE(cur ^ 1);
        __syncthreads();
    }
    #pragma unroll
    for (int im = 0; im < 8; im++) {
        int m = m0 + MROW(im);
        int b_ = m >> 11, s_ = m & 2047;
        #pragma unroll
        for (int jn = 0; jn < 4; jn++) {
            int n = n0 + NCOL(jn);
            float2 v = unpk(acc[im][jn]);
            int head = n >> 6, d = n & 63;
            *(float2*)&dst[((size_t)(b_*8 + head)*2048 + s_)*64 + d] =
                make_float2(v.x + bias[n], v.y + bias[n+1]);
        }
    }
}

// ==================================================== Kp / Vp ==============
__device__ __forceinline__ void fma2s(u64& d, float a, u64 b) {
    u64 ad; unsigned ai = __float_as_uint(a);
    asm("mov.b64 %0, {%1, %1};" : "=l"(ad) : "r"(ai));
    fma2(d, ad, b);
}
__global__ __launch_bounds__(256) void kpvp_kernel(
        const float* __restrict__ Wkp, const float* __restrict__ bkp,
        const float* __restrict__ Wvp, const float* __restrict__ bvp) {
    __shared__ __align__(16) float Xs[64][68];
    __shared__ __align__(16) float Ws[64][68];
    int tid = threadIdx.x;
    int pos0 = blockIdx.x * 64;
    int tx = tid & 15, ty = tid >> 4;
    int p = tid & 63, dg = tid >> 6;

    #pragma unroll
    for (int phase = 0; phase < 2; phase++) {
        const float* X = phase ? g_V : g_K;
        const float* W = phase ? Wvp : Wkp;
        const float* bias = phase ? bvp : bkp;
        float* dst = phase ? g_Vp : g_Kp;
        {
            const float* Xr = &X[((size_t)(pos0 + p))*64 + dg*16];
            const float* Wr = &W[(size_t)p*64 + dg*16];
            #pragma unroll
            for (int i = 0; i < 4; i++) {
                float4 xv = *(const float4*)(Xr + i*4);
                float4 wv = *(const float4*)(Wr + i*4);
                int d = dg*16 + i*4;
                Xs[d][p]=xv.x; Xs[d+1][p]=xv.y; Xs[d+2][p]=xv.z; Xs[d+3][p]=xv.w;
                Ws[d][p]=wv.x; Ws[d+1][p]=wv.y; Ws[d+2][p]=wv.z; Ws[d+3][p]=wv.w;
            }
        }
        __syncthreads();
        {
            u64 acc[4][2] = {};
            #pragma unroll 4
            for (int d = 0; d < 64; d++) {
                u64 b0 = *(const u64*)&Ws[d][tx*4];
                u64 b1 = *(const u64*)&Ws[d][tx*4 + 2];
                const float* Xr = &Xs[d][ty*4];
                fma2s(acc[0][0], Xr[0], b0); fma2s(acc[0][1], Xr[0], b1);
                fma2s(acc[1][0], Xr[1], b0); fma2s(acc[1][1], Xr[1], b1);
                fma2s(acc[2][0], Xr[2], b0); fma2s(acc[2][1], Xr[2], b1);
                fma2s(acc[3][0], Xr[3], b0); fma2s(acc[3][1], Xr[3], b1);
            }
            float b0v = bias[tx*4], b1v = bias[tx*4+1], b2v = bias[tx*4+2], b3v = bias[tx*4+3];
            #pragma unroll
            for (int i = 0; i < 4; i++) {
                float2 p0 = unpk(acc[i][0]);
                float2 p1 = unpk(acc[i][1]);
                float4 o = make_float4(p0.x+b0v, p0.y+b1v, p1.x+b2v, p1.y+b3v);
                *(float4*)&dst[((size_t)(pos0 + ty*4 + i))*64 + tx*4] = o;
            }
        }
        __syncthreads();
    }
}

// ======================================== scores GEMM (per-bh) =============
__global__ __launch_bounds__(256, 2) void scores_kernel(int bh) {
    __shared__ __align__(16) float As[2][16][264];
    __shared__ __align__(16) float Bs[2][16][132];
    int m0 = blockIdx.y * 128;
    int n0 = blockIdx.x * 128;
    const float* A = g_Q  + (size_t)bh*2048*64;
    const float* B = g_Kp + (size_t)bh*2048*64;

    int tid = threadIdx.x;
    int tx = tid & 15, ty = tid >> 4;
    int lrow = tid >> 2, lcg = tid & 3;
    u64 acc[8][4] = {};
    const float* Ap0 = &A[(size_t)(m0+lrow)*64    + lcg*4];
    const float* Ap1 = &A[(size_t)(m0+lrow+64)*64 + lcg*4];
    const float* Wp0 = &B[(size_t)(n0+lrow)*64    + lcg*4];
    const float* Wp1 = &B[(size_t)(n0+lrow+64)*64 + lcg*4];

    {
        float4 sa0 = *(const float4*)Ap0;
        float4 sa1 = *(const float4*)Ap1;
        float4 sw0 = *(const float4*)Wp0;
        float4 sw1 = *(const float4*)Wp1;
        STORE_TILE(0);
    }
    __syncthreads();

    #pragma unroll 1
    for (int kt = 0; kt < 4; kt++) {
        int cur = kt & 1;
        float4 sa0, sa1, sw0, sw1;
        if (kt < 3) {
            int k0 = (kt+1)*16;
            sa0 = *(const float4*)(Ap0 + k0);
            sa1 = *(const float4*)(Ap1 + k0);
            sw0 = *(const float4*)(Wp0 + k0);
            sw1 = *(const float4*)(Wp1 + k0);
        }
        COMPUTE_TILE(cur);
        if (kt < 3) STORE_TILE(cur ^ 1);
        __syncthreads();
    }
    #pragma unroll
    for (int im = 0; im < 8; im++) {
        int m = MROW(im);
        size_t rowb = ((size_t)(bh*2048 + m0 + m))*2048 + n0;
        float2 u0 = unpk(acc[im][0]);
        float2 u1 = unpk(acc[im][1]);
        float2 u2 = unpk(acc[im][2]);
        float2 u3 = unpk(acc[im][3]);
        *(float4*)&g_gs[rowb + tx*4] =
            make_float4(u0.x*0.125f, u0.y*0.125f, u1.x*0.125f, u1.y*0.125f);
        *(float4*)&g_gs[rowb + 64 + tx*4] =
            make_float4(u2.x*0.125f, u2.y*0.125f, u3.x*0.125f, u3.y*0.125f);
    }
}

// ======================================== top-16 + softmax (per-bh) ========
__device__ __forceinline__ u64 pack_vi(float val, int idx) {
    unsigned bits = __float_as_uint(val);
    unsigned mono = bits ^ ((unsigned)(((int)bits) >> 31) | 0x80000000u);
    return ((u64)mono << 32) | (unsigned)(~idx);
}
__device__ __forceinline__ u64 umax64(u64 a, u64 b) { return a > b ? a : b; }
__device__ __forceinline__ u64 wmax(u64 m) {
    #pragma unroll
    for (int o = 16; o > 0; o >>= 1) {
        u64 x = __shfl_xor_sync(0xffffffffu, m, o);
        m = x > m ? x : m;
    }
    return m;
}
__device__ __forceinline__ float wmaxf(float m) {
    #pragma unroll
    for (int o = 16; o > 0; o >>= 1)
        m = fmaxf(m, __shfl_xor_sync(0xffffffffu, m, o));
    return m;
}
__device__ __forceinline__ void try_insert(u64* t, float val, int kidx) {
    u64 p = pack_vi(val, kidx);
    if (p > t[15]) {
        #pragma unroll
        for (int j = 15; j > 0; j--)
            t[j] = (p > t[j-1]) ? t[j-1] : ((p > t[j]) ? p : t[j]);
        t[0] = (p > t[0]) ? p : t[0];
    }
}
__device__ __noinline__ void topk_slow_warp(const float4* row, int lane,
                                            u64& mine, u64& top0) {
    u64 t[16];
    #pragma unroll
    for (int j = 0; j < 16; j++) t[j] = 0;
    for (int i = 0; i < 16; i++) {
        float4 v = row[i*32 + lane];
        int kb = (i*32 + lane)*4;
        try_insert(t, v.x, kb);   try_insert(t, v.y, kb+1);
        try_insert(t, v.z, kb+2); try_insert(t, v.w, kb+3);
    }
    for (int r = 0; r < 16; r++) {
        u64 c = t[0];
        u64 m = wmax(c);
        if (r == 0) top0 = m;
        if (lane == r) mine = m;
        if (c == m) {
            #pragma unroll
            for (int j = 0; j < 15; j++) t[j] = t[j+1];
            t[15] = 0;
        }
    }
}

__global__ __launch_bounds__(256) void topk_kernel(int gq0) {
    __shared__ u64 sbuf[8][SCAP];
    int warp = threadIdx.x >> 5, lane = threadIdx.x & 31;
    int gq = gq0 + blockIdx.x*8 + warp;
    const float4* row = (const float4*)(g_gs + (size_t)gq*2048);

    float lmax = -INFINITY;
    #pragma unroll
    for (int i = 0; i < 16; i += 4) {
        float4 v0 = row[(i+0)*32 + lane];
        float4 v1 = row[(i+1)*32 + lane];
        float4 v2 = row[(i+2)*32 + lane];
        float4 v3 = row[(i+3)*32 + lane];
        lmax = fmaxf(lmax, fmaxf(fmaxf(v0.x, v0.y), fmaxf(v0.z, v0.w)));
        lmax = fmaxf(lmax, fmaxf(fmaxf(v1.x, v1.y), fmaxf(v1.z, v1.w)));
        lmax = fmaxf(lmax, fmaxf(fmaxf(v2.x, v2.y), fmaxf(v2.z, v2.w)));
        lmax = fmaxf(lmax, fmaxf(fmaxf(v3.x, v3.y), fmaxf(v3.z, v3.w)));
    }

    float curf = lmax, T = 0.f;
    #pragma unroll 1
    for (int r = 0; r < 16; r++) {
        float m = wmaxf(curf);
        if (curf == m) curf = -INFINITY;
        T = m;
    }

    int cnt = 0;
    #pragma unroll 1
    for (int i = 0; i < 16; i++) {
        float4 v = row[i*32 + lane];
        int kb = (i*32 + lane)*4;
        float vs[4] = {v.x, v.y, v.z, v.w};
        #pragma unroll
        for (int j = 0; j < 4; j++) {
            bool keep = vs[j] >= T;
            unsigned ball = __ballot_sync(0xffffffffu, keep);
            int pos = cnt + __popc(ball & ((1u << lane) - 1u));
            if (keep && pos < SCAP) sbuf[warp][pos] = pack_vi(vs[j], kb + j);
            cnt += __popc(ball);
        }
    }

    u64 mine = 0, top0 = 0;
    if (cnt <= SCAP) {
        u64 ple[SCAP/32];
        #pragma unroll
        for (int j = 0; j < SCAP/32; j++) {
            int ii = lane + j*32;
            ple[j] = (ii < cnt) ? sbuf[warp][ii] : 0;
        }
        u64 lm = 0;
        #pragma unroll
        for (int j = 0; j < SCAP/32; j++) lm = umax64(lm, ple[j]);
        #pragma unroll 1
        for (int r = 0; r < 16; r++) {
            u64 m = wmax(lm);
            if (r == 0) top0 = m;
            if (lane == r) mine = m;
            lm = 0;
            #pragma unroll
            for (int j = 0; j < SCAP/32; j++) {
                ple[j] = (ple[j] == m) ? 0 : ple[j];
                lm = umax64(lm, ple[j]);
            }
        }
    } else {
        topk_slow_warp(row, lane, mine, top0);
    }

    unsigned mtop = (unsigned)(top0 >> 32);
    float vmax = __uint_as_float((mtop >> 31) ? (mtop ^ 0x80000000u) : ~mtop);
    float e = 0.f; int idx = 0;
    if (lane < 16) {
        unsigned mm = (unsigned)(mine >> 32);
        float v = __uint_as_float((mm >> 31) ? (mm ^ 0x80000000u) : ~mm);
        e = expf(v - vmax);
        idx = (int)(~(unsigned)mine);
    }
    float s = e;
    #pragma unroll
    for (int o = 16; o > 0; o >>= 1) s += __shfl_xor_sync(0xffffffffu, s, o);
    if (lane < 16) {
        g_tw[(size_t)gq*16 + lane]  = e / s;
        g_tix[(size_t)gq*16 + lane] = idx;
    }
}

// ======================================== sparse gather + Wvp proj =========
__global__ __launch_bounds__(256) void spout_kernel(const float* __restrict__ Wvp,
                                                    const float* __restrict__ bvp) {
    __shared__ float Ws[64][65];
    __shared__ float sps[8][64];
    int tid = threadIdx.x;
    int warp = tid >> 5, lane = tid & 31;

    #pragma unroll
    for (int i = 0; i < 16; i++) {
        int e = tid + i*256;
        int d = e >> 6, r = e & 63;
        Ws[d][r] = Wvp[(size_t)d*64 + r];
    }
    __syncthreads();

    int gq = blockIdx.x*8 + warp;
    int bh = gq >> 11;
    const float* Vb = g_Vp + (size_t)bh*2048*64;

    float w[TK]; int ix[TK];
    #pragma unroll
    for (int k = 0; k < TK; k++) {
        w[k]  = g_tw[(size_t)gq*16 + k];
        ix[k] = g_tix[(size_t)gq*16 + k];
    }
    float a0 = 0.f, a1 = 0.f;
    #pragma unroll
    for (int k = 0; k < TK; k++) {
        const float* Vr = Vb + (size_t)ix[k]*64;
        a0 += w[k]*Vr[lane];
        a1 += w[k]*Vr[lane + 32];
    }
    sps[warp][lane] = a0;
    sps[warp][lane + 32] = a1;
    __syncwarp();

    float o0 = bvp[lane], o1 = bvp[lane + 32];
    #pragma unroll 8
    for (int r = 0; r < 64; r++) {
        float sv = sps[warp][r];
        o0 += sv * Ws[lane][r];
        o1 += sv * Ws[lane + 32][r];
    }
    int b_ = gq >> 14, hh = (gq >> 11) & 7, s_ = gq & 2047;
    size_t base = ((size_t)(b_*2048 + s_))*512 + hh*64;
    g_sp[base + lane]      = o0;
    g_sp[base + lane + 32] = o1;
}

// ============================================ local window attention =======
__global__ void local_kernel() {
    int warp = threadIdx.x >> 5, lane = threadIdx.x & 31;
    int gq = blockIdx.x*8 + warp;
    int bh = gq >> 11, s = gq & 2047;
    const float* Qr = g_Q + (size_t)gq*64;
    float q0 = Qr[lane], q1 = Qr[lane + 32];
    float sc[5];
    #pragma unroll
    for (int w = 0; w < 5; w++) {
        int j = s - 2 + w;
        float v = -INFINITY;
        if (j >= 0 && j < S) {
            const float* Kr = g_K + ((size_t)bh*S + j)*64;
            float p = q0*Kr[lane] + q1*Kr[lane+32];
            #pragma unroll
            for (int o = 16; o > 0; o >>= 1) p += __shfl_xor_sync(0xffffffffu, p, o);
            v = p * 0.125f;
        }
        sc[w] = v;
    }
    float m = sc[0];
    #pragma unroll
    for (int w = 1; w < 5; w++) m = fmaxf(m, sc[w]);
    float e[5], ssum = 0.f;
    #pragma unroll
    for (int w = 0; w < 5; w++) { e[w] = expf(sc[w] - m); ssum += e[w]; }
    float inv = 1.f / ssum;
    float o0 = 0.f, o1 = 0.f;
    #pragma unroll
    for (int w = 0; w < 5; w++) {
        int j = s - 2 + w;
        if (j >= 0 && j < S) {
            const float* Vr = g_V + ((size_t)bh*S + j)*64;
            float p = e[w]*inv;
            o0 += p*Vr[lane]; o1 += p*Vr[lane+32];
        }
    }
    int b = bh >> 3, hh = bh & 7;
    g_attn[(size_t)(b*S + s)*512 + hh*64 + lane]      = o0;
    g_attn[(size_t)(b*S + s)*512 + hh*64 + lane + 32] = o1;
}

// ======================================== output proj ======================
__global__ __launch_bounds__(256, 2) void outproj_kernel(const float* __restrict__ Wo,
                                                         const float* __restrict__ bo) {
    __shared__ __align__(16) float As[2][16][264];
    __shared__ __align__(16) float Bs[2][16][132];
    int m0 = blockIdx.x * 128;
    int n0 = blockIdx.y * 128;
    int tid = threadIdx.x;
    int tx = tid & 15, ty = tid >> 4;
    int lrow = tid >> 2, lcg = tid & 3;
    u64 acc[8][4] = {};
    size_t ia0 = (size_t)(m0+lrow)*512    + lcg*4;
    size_t ia1 = (size_t)(m0+lrow+64)*512 + lcg*4;
    const float* Wp0 = &Wo[(size_t)(n0+lrow)*512    + lcg*4];
    const float* Wp1 = &Wo[(size_t)(n0+lrow+64)*512 + lcg*4];

    {
        float4 x0 = *(const float4*)&g_attn[ia0];
        float4 x1 = *(const float4*)&g_attn[ia1];
        float4 p0 = *(const float4*)&g_sp[ia0];
        float4 p1 = *(const float4*)&g_sp[ia1];
        float4 sa0 = make_float4(0.5f*(x0.x+p0.x), 0.5f*(x0.y+p0.y),
                                 0.5f*(x0.z+p0.z), 0.5f*(x0.w+p0.w));
        float4 sa1 = make_float4(0.5f*(x1.x+p1.x), 0.5f*(x1.y+p1.y),
                                 0.5f*(x1.z+p1.z), 0.5f*(x1.w+p1.w));
        float4 sw0 = *(const float4*)Wp0;
        float4 sw1 = *(const float4*)Wp1;
        STORE_TILE(0);
    }
    __syncthreads();

    #pragma unroll 1
    for (int kt = 0; kt < 32; kt++) {
        int cur = kt & 1;
        float4 sa0, sa1, sw0, sw1;
        if (kt < 31) {
            int k0 = (kt+1)*16;
            float4 x0 = *(const float4*)&g_attn[ia0 + k0];
            float4 x1 = *(const float4*)&g_attn[ia1 + k0];
            float4 p0 = *(const float4*)&g_sp[ia0 + k0];
            float4 p1 = *(const float4*)&g_sp[ia1 + k0];
            sa0 = make_float4(0.5f*(x0.x+p0.x), 0.5f*(x0.y+p0.y),
                              0.5f*(x0.z+p0.z), 0.5f*(x0.w+p0.w));
            sa1 = make_float4(0.5f*(x1.x+p1.x), 0.5f*(x1.y+p1.y),
                              0.5f*(x1.z+p1.z), 0.5f*(x1.w+p1.w));
            sw0 = *(const float4*)(Wp0 + k0);
            sw1 = *(const float4*)(Wp1 + k0);
        }
        COMPUTE_TILE(cur);
        if (kt < 31) STORE_TILE(cur ^ 1);
        __syncthreads();
    }
    #pragma unroll
    for (int im = 0; im < 8; im++) {
        int m = m0 + MROW(im);
        #pragma unroll
        for (int jn = 0; jn < 4; jn++) {
            int n = n0 + NCOL(jn);
            float2 v = unpk(acc[im][jn]);
            float2 h = *(const float2*)&g_h[(size_t)m*512 + n];
            *(float2*)&g_res[(size_t)m*512 + n] =
                make_float2(v.x + bo[n] + h.x, v.y + bo[n+1] + h.y);
        }
    }
}

// ================================================== layernorm ==============
__global__ void ln_kernel(const float* __restrict__ g, const float* __restrict__ bta,
                          float* __restrict__ out) {
    int row = blockIdx.x, tid = threadIdx.x;
    const float* rr = g_res + (size_t)row*512;
    float v0 = rr[tid], v1 = rr[tid + 256];
    float s = v0 + v1, sq = v0*v0 + v1*v1;
    __shared__ float rs[8], rq[8];
    #pragma unroll
    for (int o = 16; o > 0; o >>= 1) {
        s  += __shfl_xor_sync(0xffffffffu, s, o);
        sq += __shfl_xor_sync(0xffffffffu, sq, o);
    }
    if ((tid & 31) == 0) { rs[tid >> 5] = s; rq[tid >> 5] = sq; }
    __syncthreads();
    float ts = 0.f, tq = 0.f;
    #pragma unroll
    for (int i = 0; i < 8; i++) { ts += rs[i]; tq += rq[i]; }
    float mu = ts * (1.f/512.f);
    float var = tq * (1.f/512.f) - mu*mu;
    float rstd = rsqrtf(var + 1e-5f);
    out[(size_t)row*512 + tid]       = (v0 - mu)*rstd*g[tid]       + bta[tid];
    out[(size_t)row*512 + tid + 256] = (v1 - mu)*rstd*g[tid + 256] + bta[tid + 256];
}

// ==================================================== launch ===============
extern "C" void kernel_launch(void* const* d_in, const int* in_sizes, int n_in,
                              void* d_out, int out_size) {
    const float* x   = (const float*)d_in[0];
    const float* w1  = (const float*)d_in[1];
    const float* b1  = (const float*)d_in[2];
    const float* w2  = (const float*)d_in[3];
    const float* b2  = (const float*)d_in[4];
    const float* w3  = (const float*)d_in[5];
    const float* b3  = (const float*)d_in[6];
    const float* Wq  = (const float*)d_in[7];
    const float* bq  = (const float*)d_in[8];
    const float* Wk  = (const float*)d_in[9];
    const float* bk  = (const float*)d_in[10];
    const float* Wv  = (const float*)d_in[11];
    const float* bv  = (const float*)d_in[12];
    const float* Wkp = (const float*)d_in[13];
    const float* bkp = (const float*)d_in[14];
    const float* Wvp = (const float*)d_in[15];
    const float* bvp = (const float*)d_in[16];
    const float* Wo  = (const float*)d_in[17];
    const float* bo  = (const float*)d_in[18];
    const float* lng = (const float*)d_in[19];
    const float* lnb = (const float*)d_in[20];
    float* out = (float*)d_out;

    xcol_kernel<<<4096*112/256, 256>>>(x);
    wpad_kernel<<<512*448/256, 256>>>(w1, w2, w3);
    conv_gemm_kernel<<<dim3(4096/128, 4), 256>>>(b1, b2, b3);
    qkv_kernel<<<dim3(4096/128, 12), 256>>>(Wq, bq, Wk, bk, Wv, bv);   // 4th: profiled
    kpvp_kernel<<<32768/64, 256>>>(Wkp, bkp, Wvp, bvp);
    for (int bh = 0; bh < 16; bh++) {          // L2-resident scores -> topk
        scores_kernel<<<dim3(16, 16), 256>>>(bh);
        topk_kernel<<<2048/8, 256>>>(bh*2048);
    }
    local_kernel<<<32768/8, 256>>>();
    spout_kernel<<<32768/8, 256>>>(Wvp, bvp);
    outproj_kernel<<<dim3(4096/128, 4), 256>>>(Wo, bo);
    ln_kernel<<<4096, 256>>>(lng, lnb, out);
}

// round 14
// speedup vs baseline: 1.4888x; 1.4888x over previous
#include <cuda_runtime.h>
#include <math.h>

typedef unsigned long long u64;
#define S 2048
#define TK 16
#define SCAP 128

__device__ float g_h[4096*512];
__device__ float g_xcol[4096*448];
__device__ float g_W7[512*448];
__device__ float g_Q[32768*64];
__device__ float g_K[32768*64];
__device__ float g_V[32768*64];
__device__ float g_Kp[32768*64];
__device__ float g_Vp[32768*64];
__device__ float g_gs[32768*2048];
__device__ float g_tw[32768*16];
__device__ int   g_tix[32768*16];
__device__ float g_sp[4096*512];      // 0.5*(local + sparse) combined
__device__ float g_res[4096*512];

__device__ __forceinline__ void fma2(u64& d, u64 a, u64 b) {
    asm("fma.rn.f32x2 %0, %1, %2, %0;" : "+l"(d) : "l"(a), "l"(b));
}
__device__ __forceinline__ u64 dup2(float x) {
    u64 r; unsigned xi = __float_as_uint(x);
    asm("mov.b64 %0, {%1, %1};" : "=l"(r) : "r"(xi));
    return r;
}
__device__ __forceinline__ float2 unpk(u64 v) {
    unsigned lo, hi;
    asm("mov.b64 {%0, %1}, %2;" : "=r"(lo), "=r"(hi) : "l"(v));
    return make_float2(__uint_as_float(lo), __uint_as_float(hi));
}

#define STORE_TILE(b) do { \
    As[b][lcg*4+0][lrow] = sa0.x; As[b][lcg*4+1][lrow] = sa0.y; \
    As[b][lcg*4+2][lrow] = sa0.z; As[b][lcg*4+3][lrow] = sa0.w; \
    As[b][lcg*4+0][lrow+64] = sa1.x; As[b][lcg*4+1][lrow+64] = sa1.y; \
    As[b][lcg*4+2][lrow+64] = sa1.z; As[b][lcg*4+3][lrow+64] = sa1.w; \
    Bs[b][lcg*4+0][lrow] = sw0.x; Bs[b][lcg*4+1][lrow] = sw0.y; \
    Bs[b][lcg*4+2][lrow] = sw0.z; Bs[b][lcg*4+3][lrow] = sw0.w; \
    Bs[b][lcg*4+0][lrow+64] = sw1.x; Bs[b][lcg*4+1][lrow+64] = sw1.y; \
    Bs[b][lcg*4+2][lrow+64] = sw1.z; Bs[b][lcg*4+3][lrow+64] = sw1.w; \
} while (0)

#define COMPUTE_TILE(b) do { \
    _Pragma("unroll") \
    for (int kk = 0; kk < 16; kk++) { \
        const float* Ar = As[b][kk]; \
        const float* Br = Bs[b][kk]; \
        u64 a2[4]; \
        a2[0] = *(const u64*)(Ar + ty*4); \
        a2[1] = *(const u64*)(Ar + ty*4 + 2); \
        a2[2] = *(const u64*)(Ar + 64 + ty*4); \
        a2[3] = *(const u64*)(Ar + 64 + ty*4 + 2); \
        float4 b0 = *(const float4*)(Br + tx*4); \
        float4 b1 = *(const float4*)(Br + 64 + tx*4); \
        u64 bd[8] = {dup2(b0.x), dup2(b0.y), dup2(b0.z), dup2(b0.w), \
                     dup2(b1.x), dup2(b1.y), dup2(b1.z), dup2(b1.w)}; \
        _Pragma("unroll") \
        for (int im = 0; im < 4; im++) \
            _Pragma("unroll") \
            for (int jn = 0; jn < 8; jn++) \
                fma2(acc[im][jn], a2[im], bd[jn]); \
    } \
} while (0)

// ======================================== conv prep: im2col + padded W =====
__global__ __launch_bounds__(256) void xcol_kernel(const float* __restrict__ x) {
    int idx = blockIdx.x*256 + threadIdx.x;
    int s = idx / 112;
    int r = idx % 112;
    int t = r >> 4, icg = r & 15;
    int b = s >> 11, ss = s & 2047;
    int s_in = ss - 3 + t;
    float4 v = make_float4(0.f, 0.f, 0.f, 0.f);
    if (s_in >= 0 && s_in < S)
        v = *(const float4*)&x[((size_t)(b*S + s_in))*64 + icg*4];
    *(float4*)&g_xcol[(size_t)s*448 + t*64 + icg*4] = v;
}

__global__ __launch_bounds__(256) void wpad_kernel(
        const float* __restrict__ w1, const float* __restrict__ w2,
        const float* __restrict__ w3) {
    int idx = blockIdx.x*256 + threadIdx.x;
    int oc = idx / 448;
    int k  = idx % 448;
    int t = k >> 6, ic = k & 63;
    float val = 0.f;
    if (oc < 171) {
        int tt = t - 2;
        if (tt >= 0 && tt < 3) val = w1[(oc*64 + ic)*3 + tt];
    } else if (oc < 342) {
        int tt = t - 1, o = oc - 171;
        if (tt >= 0 && tt < 5) val = w2[(o*64 + ic)*5 + tt];
    } else {
        int o = oc - 342;
        val = w3[(o*64 + ic)*7 + t];
    }
    g_W7[(size_t)oc*448 + k] = val;
}

// ======================================== conv GEMM (1-sync double buffer) =
__global__ __launch_bounds__(256, 2) void conv_gemm_kernel(
        const float* __restrict__ b1, const float* __restrict__ b2,
        const float* __restrict__ b3) {
    __shared__ __align__(16) float As[2][16][132];
    __shared__ __align__(16) float Bs[2][16][132];
    int m0 = blockIdx.x * 128;
    int n0 = blockIdx.y * 128;
    int tid = threadIdx.x;
    int tx = tid & 15, ty = tid >> 4;
    int lrow = tid >> 2, lcg = tid & 3;
    u64 acc[4][8] = {};
    const float* Ap0 = &g_xcol[(size_t)(m0+lrow)*448    + lcg*4];
    const float* Ap1 = &g_xcol[(size_t)(m0+lrow+64)*448 + lcg*4];
    const float* Wp0 = &g_W7[(size_t)(n0+lrow)*448      + lcg*4];
    const float* Wp1 = &g_W7[(size_t)(n0+lrow+64)*448   + lcg*4];

    {
        float4 sa0 = *(const float4*)Ap0;
        float4 sa1 = *(const float4*)Ap1;
        float4 sw0 = *(const float4*)Wp0;
        float4 sw1 = *(const float4*)Wp1;
        STORE_TILE(0);
    }
    __syncthreads();

    #pragma unroll 1
    for (int kt = 0; kt < 28; kt++) {
        int cur = kt & 1;
        float4 sa0, sa1, sw0, sw1;
        if (kt < 27) {
            int k0 = (kt+1)*16;
            sa0 = *(const float4*)(Ap0 + k0);
            sa1 = *(const float4*)(Ap1 + k0);
            sw0 = *(const float4*)(Wp0 + k0);
            sw1 = *(const float4*)(Wp1 + k0);
        }
        COMPUTE_TILE(cur);
        if (kt < 27) STORE_TILE(cur ^ 1);
        __syncthreads();
    }
    #pragma unroll
    for (int im = 0; im < 4; im++) {
        int mloc = (im >> 1)*64 + ty*4 + (im & 1)*2;
        #pragma unroll
        for (int jn = 0; jn < 8; jn++) {
            int nloc = (jn >> 2)*64 + tx*4 + (jn & 3);
            float2 v = unpk(acc[im][jn]);
            int n = n0 + nloc;
            float bb = (n < 171) ? b1[n] : (n < 342 ? b2[n-171] : b3[n-342]);
            size_t i0 = (size_t)(m0 + mloc)*512 + n;
            g_h[i0]       = fmaxf(v.x + bb, 0.f);
            g_h[i0 + 512] = fmaxf(v.y + bb, 0.f);
        }
    }
}

// ======================================== qkv GEMM (1-sync double buffer) ==
__global__ __launch_bounds__(256, 2) void qkv_kernel(
        const float* __restrict__ Wq, const float* __restrict__ bq,
        const float* __restrict__ Wk, const float* __restrict__ bk,
        const float* __restrict__ Wv, const float* __restrict__ bv) {
    __shared__ __align__(16) float As[2][16][132];
    __shared__ __align__(16) float Bs[2][16][132];
    int m0 = blockIdx.x * 128;
    int by = blockIdx.y;
    const float *W, *bias; float* dst;
    if (by < 4)      { W = Wq; bias = bq; dst = g_Q; }
    else if (by < 8) { W = Wk; bias = bk; dst = g_K; }
    else             { W = Wv; bias = bv; dst = g_V; }
    int n0 = (by & 3) * 128;

    int tid = threadIdx.x;
    int tx = tid & 15, ty = tid >> 4;
    int lrow = tid >> 2, lcg = tid & 3;
    u64 acc[4][8] = {};
    const float* Ap0 = &g_h[(size_t)(m0+lrow)*512    + lcg*4];
    const float* Ap1 = &g_h[(size_t)(m0+lrow+64)*512 + lcg*4];
    const float* Wp0 = &W[(size_t)(n0+lrow)*512      + lcg*4];
    const float* Wp1 = &W[(size_t)(n0+lrow+64)*512   + lcg*4];

    {
        float4 sa0 = *(const float4*)Ap0;
        float4 sa1 = *(const float4*)Ap1;
        float4 sw0 = *(const float4*)Wp0;
        float4 sw1 = *(const float4*)Wp1;
        STORE_TILE(0);
    }
    __syncthreads();

    #pragma unroll 1
    for (int kt = 0; kt < 32; kt++) {
        int cur = kt & 1;
        float4 sa0, sa1, sw0, sw1;
        if (kt < 31) {
            int k0 = (kt+1)*16;
            sa0 = *(const float4*)(Ap0 + k0);
            sa1 = *(const float4*)(Ap1 + k0);
            sw0 = *(const float4*)(Wp0 + k0);
            sw1 = *(const float4*)(Wp1 + k0);
        }
        COMPUTE_TILE(cur);
        if (kt < 31) STORE_TILE(cur ^ 1);
        __syncthreads();
    }
    #pragma unroll
    for (int im = 0; im < 4; im++) {
        int mloc = (im >> 1)*64 + ty*4 + (im & 1)*2;
        #pragma unroll
        for (int jn = 0; jn < 8; jn++) {
            int nloc = (jn >> 2)*64 + tx*4 + (jn & 3);
            float2 v = unpk(acc[im][jn]);
            int n = n0 + nloc;
            float bb = bias[n];
            int head = n >> 6, d = n & 63;
            int m = m0 + mloc;
            int b_ = m >> 11, s_ = m & 2047;
            dst[((size_t)(b_*8 + head)*2048 + s_)*64 + d] = v.x + bb;
            m++; b_ = m >> 11; s_ = m & 2047;
            dst[((size_t)(b_*8 + head)*2048 + s_)*64 + d] = v.y + bb;
        }
    }
}

// ==================================================== Kp / Vp ==============
__global__ __launch_bounds__(256) void kpvp_kernel(
        const float* __restrict__ Wkp, const float* __restrict__ bkp,
        const float* __restrict__ Wvp, const float* __restrict__ bvp) {
    __shared__ __align__(16) float Xs[64][68];
    __shared__ __align__(16) float Ws[64][68];
    int tid = threadIdx.x;
    int pos0 = blockIdx.x * 64;
    int tx = tid & 15, ty = tid >> 4;
    int p = tid & 63, dg = tid >> 6;

    #pragma unroll
    for (int phase = 0; phase < 2; phase++) {
        const float* X = phase ? g_V : g_K;
        const float* W = phase ? Wvp : Wkp;
        const float* bias = phase ? bvp : bkp;
        float* dst = phase ? g_Vp : g_Kp;
        {
            const float* Xr = &X[((size_t)(pos0 + p))*64 + dg*16];
            const float* Wr = &W[(size_t)p*64 + dg*16];
            #pragma unroll
            for (int i = 0; i < 4; i++) {
                float4 xv = *(const float4*)(Xr + i*4);
                float4 wv = *(const float4*)(Wr + i*4);
                int d = dg*16 + i*4;
                Xs[d][p]=xv.x; Xs[d+1][p]=xv.y; Xs[d+2][p]=xv.z; Xs[d+3][p]=xv.w;
                Ws[d][p]=wv.x; Ws[d+1][p]=wv.y; Ws[d+2][p]=wv.z; Ws[d+3][p]=wv.w;
            }
        }
        __syncthreads();
        {
            u64 acc[4][2] = {};
            #pragma unroll 4
            for (int d = 0; d < 64; d++) {
                u64 b0 = *(const u64*)&Ws[d][tx*4];
                u64 b1 = *(const u64*)&Ws[d][tx*4 + 2];
                const float* Xr = &Xs[d][ty*4];
                u64 a0 = dup2(Xr[0]), a1 = dup2(Xr[1]), a2 = dup2(Xr[2]), a3 = dup2(Xr[3]);
                fma2(acc[0][0], a0, b0); fma2(acc[0][1], a0, b1);
                fma2(acc[1][0], a1, b0); fma2(acc[1][1], a1, b1);
                fma2(acc[2][0], a2, b0); fma2(acc[2][1], a2, b1);
                fma2(acc[3][0], a3, b0); fma2(acc[3][1], a3, b1);
            }
            float b0v = bias[tx*4], b1v = bias[tx*4+1], b2v = bias[tx*4+2], b3v = bias[tx*4+3];
            #pragma unroll
            for (int i = 0; i < 4; i++) {
                float2 p0 = unpk(acc[i][0]);
                float2 p1 = unpk(acc[i][1]);
                float4 o = make_float4(p0.x+b0v, p0.y+b1v, p1.x+b2v, p1.y+b3v);
                *(float4*)&dst[((size_t)(pos0 + ty*4 + i))*64 + tx*4] = o;
            }
        }
        __syncthreads();
    }
}

// ======================================== scores GEMM (1-sync db) ==========
__global__ __launch_bounds__(256, 2) void scores_kernel() {
    __shared__ __align__(16) float As[2][16][132];
    __shared__ __align__(16) float Bs[2][16][132];
    int bh = blockIdx.z;
    int m0 = blockIdx.y * 128;
    int n0 = blockIdx.x * 128;
    const float* A = g_Q  + (size_t)bh*2048*64;
    const float* B = g_Kp + (size_t)bh*2048*64;

    int tid = threadIdx.x;
    int tx = tid & 15, ty = tid >> 4;
    int lrow = tid >> 2, lcg = tid & 3;
    u64 acc[4][8] = {};
    const float* Ap0 = &A[(size_t)(m0+lrow)*64    + lcg*4];
    const float* Ap1 = &A[(size_t)(m0+lrow+64)*64 + lcg*4];
    const float* Wp0 = &B[(size_t)(n0+lrow)*64    + lcg*4];
    const float* Wp1 = &B[(size_t)(n0+lrow+64)*64 + lcg*4];

    {
        float4 sa0 = *(const float4*)Ap0;
        float4 sa1 = *(const float4*)Ap1;
        float4 sw0 = *(const float4*)Wp0;
        float4 sw1 = *(const float4*)Wp1;
        STORE_TILE(0);
    }
    __syncthreads();

    #pragma unroll 1
    for (int kt = 0; kt < 4; kt++) {
        int cur = kt & 1;
        float4 sa0, sa1, sw0, sw1;
        if (kt < 3) {
            int k0 = (kt+1)*16;
            sa0 = *(const float4*)(Ap0 + k0);
            sa1 = *(const float4*)(Ap1 + k0);
            sw0 = *(const float4*)(Wp0 + k0);
            sw1 = *(const float4*)(Wp1 + k0);
        }
        COMPUTE_TILE(cur);
        if (kt < 3) STORE_TILE(cur ^ 1);
        __syncthreads();
    }
    #pragma unroll
    for (int im = 0; im < 4; im++) {
        int mloc = (im >> 1)*64 + ty*4 + (im & 1)*2;
        float2 u[8];
        #pragma unroll
        for (int jn = 0; jn < 8; jn++) u[jn] = unpk(acc[im][jn]);
        size_t row0 = ((size_t)(bh*2048 + m0 + mloc))*2048 + n0;
        size_t row1 = row0 + 2048;
        float4 o;
        o.x=u[0].x*0.125f; o.y=u[1].x*0.125f; o.z=u[2].x*0.125f; o.w=u[3].x*0.125f;
        *(float4*)&g_gs[row0 + tx*4] = o;
        o.x=u[4].x*0.125f; o.y=u[5].x*0.125f; o.z=u[6].x*0.125f; o.w=u[7].x*0.125f;
        *(float4*)&g_gs[row0 + 64 + tx*4] = o;
        o.x=u[0].y*0.125f; o.y=u[1].y*0.125f; o.z=u[2].y*0.125f; o.w=u[3].y*0.125f;
        *(float4*)&g_gs[row1 + tx*4] = o;
        o.x=u[4].y*0.125f; o.y=u[5].y*0.125f; o.z=u[6].y*0.125f; o.w=u[7].y*0.125f;
        *(float4*)&g_gs[row1 + 64 + tx*4] = o;
    }
}

// ======================================== top-16 + softmax (warp/query) ====
__device__ __forceinline__ u64 pack_vi(float val, int idx) {
    unsigned bits = __float_as_uint(val);
    unsigned mono = bits ^ ((unsigned)(((int)bits) >> 31) | 0x80000000u);
    return ((u64)mono << 32) | (unsigned)(~idx);
}
__device__ __forceinline__ u64 umax64(u64 a, u64 b) { return a > b ? a : b; }
__device__ __forceinline__ u64 wmax(u64 m) {
    #pragma unroll
    for (int o = 16; o > 0; o >>= 1) {
        u64 x = __shfl_xor_sync(0xffffffffu, m, o);
        m = x > m ? x : m;
    }
    return m;
}
__device__ __forceinline__ float wmaxf(float m) {
    #pragma unroll
    for (int o = 16; o > 0; o >>= 1)
        m = fmaxf(m, __shfl_xor_sync(0xffffffffu, m, o));
    return m;
}
__device__ __forceinline__ void try_insert(u64* t, float val, int kidx) {
    u64 p = pack_vi(val, kidx);
    if (p > t[15]) {
        #pragma unroll
        for (int j = 15; j > 0; j--)
            t[j] = (p > t[j-1]) ? t[j-1] : ((p > t[j]) ? p : t[j]);
        t[0] = (p > t[0]) ? p : t[0];
    }
}
__device__ __noinline__ void topk_slow_warp(const float4* row, int lane,
                                            u64& mine, u64& top0) {
    u64 t[16];
    #pragma unroll
    for (int j = 0; j < 16; j++) t[j] = 0;
    for (int i = 0; i < 16; i++) {
        float4 v = row[i*32 + lane];
        int kb = (i*32 + lane)*4;
        try_insert(t, v.x, kb);   try_insert(t, v.y, kb+1);
        try_insert(t, v.z, kb+2); try_insert(t, v.w, kb+3);
    }
    for (int r = 0; r < 16; r++) {
        u64 c = t[0];
        u64 m = wmax(c);
        if (r == 0) top0 = m;
        if (lane == r) mine = m;
        if (c == m) {
            #pragma unroll
            for (int j = 0; j < 15; j++) t[j] = t[j+1];
            t[15] = 0;
        }
    }
}

__global__ __launch_bounds__(256) void topk_kernel() {
    __shared__ u64 sbuf[8][SCAP];
    int warp = threadIdx.x >> 5, lane = threadIdx.x & 31;
    int gq = blockIdx.x*8 + warp;
    const float4* row = (const float4*)(g_gs + (size_t)gq*2048);

    float lmax = -INFINITY;
    #pragma unroll
    for (int i = 0; i < 16; i += 4) {
        float4 v0 = row[(i+0)*32 + lane];
        float4 v1 = row[(i+1)*32 + lane];
        float4 v2 = row[(i+2)*32 + lane];
        float4 v3 = row[(i+3)*32 + lane];
        lmax = fmaxf(lmax, fmaxf(fmaxf(v0.x, v0.y), fmaxf(v0.z, v0.w)));
        lmax = fmaxf(lmax, fmaxf(fmaxf(v1.x, v1.y), fmaxf(v1.z, v1.w)));
        lmax = fmaxf(lmax, fmaxf(fmaxf(v2.x, v2.y), fmaxf(v2.z, v2.w)));
        lmax = fmaxf(lmax, fmaxf(fmaxf(v3.x, v3.y), fmaxf(v3.z, v3.w)));
    }

    float curf = lmax, T = 0.f;
    #pragma unroll 1
    for (int r = 0; r < 16; r++) {
        float m = wmaxf(curf);
        if (curf == m) curf = -INFINITY;
        T = m;
    }

    int cnt = 0;
    #pragma unroll 1
    for (int i = 0; i < 16; i++) {
        float4 v = row[i*32 + lane];
        int kb = (i*32 + lane)*4;
        float vs[4] = {v.x, v.y, v.z, v.w};
        #pragma unroll
        for (int j = 0; j < 4; j++) {
            bool keep = vs[j] >= T;
            unsigned ball = __ballot_sync(0xffffffffu, keep);
            int pos = cnt + __popc(ball & ((1u << lane) - 1u));
            if (keep && pos < SCAP) sbuf[warp][pos] = pack_vi(vs[j], kb + j);
            cnt += __popc(ball);
        }
    }

    u64 mine = 0, top0 = 0;
    if (cnt <= SCAP) {
        u64 ple[SCAP/32];
        #pragma unroll
        for (int j = 0; j < SCAP/32; j++) {
            int ii = lane + j*32;
            ple[j] = (ii < cnt) ? sbuf[warp][ii] : 0;
        }
        u64 lm = 0;
        #pragma unroll
        for (int j = 0; j < SCAP/32; j++) lm = umax64(lm, ple[j]);
        #pragma unroll 1
        for (int r = 0; r < 16; r++) {
            u64 m = wmax(lm);
            if (r == 0) top0 = m;
            if (lane == r) mine = m;
            lm = 0;
            #pragma unroll
            for (int j = 0; j < SCAP/32; j++) {
                ple[j] = (ple[j] == m) ? 0 : ple[j];
                lm = umax64(lm, ple[j]);
            }
        }
    } else {
        topk_slow_warp(row, lane, mine, top0);
    }

    unsigned mtop = (unsigned)(top0 >> 32);
    float vmax = __uint_as_float((mtop >> 31) ? (mtop ^ 0x80000000u) : ~mtop);
    float e = 0.f; int idx = 0;
    if (lane < 16) {
        unsigned mm = (unsigned)(mine >> 32);
        float v = __uint_as_float((mm >> 31) ? (mm ^ 0x80000000u) : ~mm);
        e = expf(v - vmax);
        idx = (int)(~(unsigned)mine);
    }
    float s = e;
    #pragma unroll
    for (int o = 16; o > 0; o >>= 1) s += __shfl_xor_sync(0xffffffffu, s, o);
    if (lane < 16) {
        g_tw[(size_t)gq*16 + lane]  = e / s;
        g_tix[(size_t)gq*16 + lane] = idx;
    }
}

// ============================ fused local attention + sparse gather/proj ===
// warp per query: local 5-window attention + top-16 gather + Wvp projection;
// writes 0.5*(local + sp) directly to g_sp.
__global__ __launch_bounds__(256) void spout_local_kernel(
        const float* __restrict__ Wvp, const float* __restrict__ bvp) {
    __shared__ float Ws[64][65];
    __shared__ float sps[8][64];
    int tid = threadIdx.x;
    int warp = tid >> 5, lane = tid & 31;

    #pragma unroll
    for (int i = 0; i < 16; i++) {
        int e = tid + i*256;
        int d = e >> 6, r = e & 63;
        Ws[d][r] = Wvp[(size_t)d*64 + r];
    }
    __syncthreads();

    int gq = blockIdx.x*8 + warp;
    int bh = gq >> 11, s = gq & 2047;

    // ---- local window attention ----
    const float* Qr = g_Q + (size_t)gq*64;
    float q0 = Qr[lane], q1 = Qr[lane + 32];
    float sc[5];
    #pragma unroll
    for (int w = 0; w < 5; w++) {
        int j = s - 2 + w;
        float v = -INFINITY;
        if (j >= 0 && j < S) {
            const float* Kr = g_K + ((size_t)bh*S + j)*64;
            float p = q0*Kr[lane] + q1*Kr[lane+32];
            #pragma unroll
            for (int o = 16; o > 0; o >>= 1) p += __shfl_xor_sync(0xffffffffu, p, o);
            v = p * 0.125f;
        }
        sc[w] = v;
    }
    float m = sc[0];
    #pragma unroll
    for (int w = 1; w < 5; w++) m = fmaxf(m, sc[w]);
    float e5[5], ssum = 0.f;
    #pragma unroll
    for (int w = 0; w < 5; w++) { e5[w] = expf(sc[w] - m); ssum += e5[w]; }
    float inv = 1.f / ssum;
    float lo0 = 0.f, lo1 = 0.f;
    #pragma unroll
    for (int w = 0; w < 5; w++) {
        int j = s - 2 + w;
        if (j >= 0 && j < S) {
            const float* Vr = g_V + ((size_t)bh*S + j)*64;
            float p = e5[w]*inv;
            lo0 += p*Vr[lane]; lo1 += p*Vr[lane+32];
        }
    }

    // ---- sparse gather ----
    const float* Vb = g_Vp + (size_t)bh*2048*64;
    float w16[TK]; int ix[TK];
    #pragma unroll
    for (int k = 0; k < TK; k++) {
        w16[k] = g_tw[(size_t)gq*16 + k];
        ix[k]  = g_tix[(size_t)gq*16 + k];
    }
    float a0 = 0.f, a1 = 0.f;
    #pragma unroll
    for (int k = 0; k < TK; k++) {
        const float* Vr = Vb + (size_t)ix[k]*64;
        a0 += w16[k]*Vr[lane];
        a1 += w16[k]*Vr[lane + 32];
    }
    sps[warp][lane] = a0;
    sps[warp][lane + 32] = a1;
    __syncwarp();

    // ---- Wvp projection + combine with local ----
    float o0 = bvp[lane], o1 = bvp[lane + 32];
    #pragma unroll 8
    for (int r = 0; r < 64; r++) {
        float sv = sps[warp][r];
        o0 += sv * Ws[lane][r];
        o1 += sv * Ws[lane + 32][r];
    }
    int b_ = gq >> 14, hh = (gq >> 11) & 7;
    size_t base = ((size_t)(b_*2048 + s))*512 + hh*64;
    g_sp[base + lane]      = 0.5f*(lo0 + o0);
    g_sp[base + lane + 32] = 0.5f*(lo1 + o1);
}

// ======================================== output proj (1-sync db) ==========
__global__ __launch_bounds__(256, 2) void outproj_kernel(const float* __restrict__ Wo,
                                                         const float* __restrict__ bo) {
    __shared__ __align__(16) float As[2][16][132];
    __shared__ __align__(16) float Bs[2][16][132];
    int m0 = blockIdx.x * 128;
    int n0 = blockIdx.y * 128;
    int tid = threadIdx.x;
    int tx = tid & 15, ty = tid >> 4;
    int lrow = tid >> 2, lcg = tid & 3;
    u64 acc[4][8] = {};
    const float* Ap0 = &g_sp[(size_t)(m0+lrow)*512    + lcg*4];
    const float* Ap1 = &g_sp[(size_t)(m0+lrow+64)*512 + lcg*4];
    const float* Wp0 = &Wo[(size_t)(n0+lrow)*512      + lcg*4];
    const float* Wp1 = &Wo[(size_t)(n0+lrow+64)*512   + lcg*4];

    {
        float4 sa0 = *(const float4*)Ap0;
        float4 sa1 = *(const float4*)Ap1;
        float4 sw0 = *(const float4*)Wp0;
        float4 sw1 = *(const float4*)Wp1;
        STORE_TILE(0);
    }
    __syncthreads();

    #pragma unroll 1
    for (int kt = 0; kt < 32; kt++) {
        int cur = kt & 1;
        float4 sa0, sa1, sw0, sw1;
        if (kt < 31) {
            int k0 = (kt+1)*16;
            sa0 = *(const float4*)(Ap0 + k0);
            sa1 = *(const float4*)(Ap1 + k0);
            sw0 = *(const float4*)(Wp0 + k0);
            sw1 = *(const float4*)(Wp1 + k0);
        }
        COMPUTE_TILE(cur);
        if (kt < 31) STORE_TILE(cur ^ 1);
        __syncthreads();
    }
    #pragma unroll
    for (int im = 0; im < 4; im++) {
        int mloc = (im >> 1)*64 + ty*4 + (im & 1)*2;
        #pragma unroll
        for (int jn = 0; jn < 8; jn++) {
            int nloc = (jn >> 2)*64 + tx*4 + (jn & 3);
            float2 v = unpk(acc[im][jn]);
            int n = n0 + nloc;
            float bb = bo[n];
            size_t i0 = (size_t)(m0 + mloc)*512 + n;
            size_t i1 = i0 + 512;
            g_res[i0] = v.x + bb + g_h[i0];
            g_res[i1] = v.y + bb + g_h[i1];
        }
    }
}

// ================================================== layernorm ==============
__global__ void ln_kernel(const float* __restrict__ g, const float* __restrict__ bta,
                          float* __restrict__ out) {
    int row = blockIdx.x, tid = threadIdx.x;
    const float* rr = g_res + (size_t)row*512;
    float v0 = rr[tid], v1 = rr[tid + 256];
    float s = v0 + v1, sq = v0*v0 + v1*v1;
    __shared__ float rs[8], rq[8];
    #pragma unroll
    for (int o = 16; o > 0; o >>= 1) {
        s  += __shfl_xor_sync(0xffffffffu, s, o);
        sq += __shfl_xor_sync(0xffffffffu, sq, o);
    }
    if ((tid & 31) == 0) { rs[tid >> 5] = s; rq[tid >> 5] = sq; }
    __syncthreads();
    float ts = 0.f, tq = 0.f;
    #pragma unroll
    for (int i = 0; i < 8; i++) { ts += rs[i]; tq += rq[i]; }
    float mu = ts * (1.f/512.f);
    float var = tq * (1.f/512.f) - mu*mu;
    float rstd = rsqrtf(var + 1e-5f);
    out[(size_t)row*512 + tid]       = (v0 - mu)*rstd*g[tid]       + bta[tid];
    out[(size_t)row*512 + tid + 256] = (v1 - mu)*rstd*g[tid + 256] + bta[tid + 256];
}

// ==================================================== launch ===============
extern "C" void kernel_launch(void* const* d_in, const int* in_sizes, int n_in,
                              void* d_out, int out_size) {
    const float* x   = (const float*)d_in[0];
    const float* w1  = (const float*)d_in[1];
    const float* b1  = (const float*)d_in[2];
    const float* w2  = (const float*)d_in[3];
    const float* b2  = (const float*)d_in[4];
    const float* w3  = (const float*)d_in[5];
    const float* b3  = (const float*)d_in[6];
    const float* Wq  = (const float*)d_in[7];
    const float* bq  = (const float*)d_in[8];
    const float* Wk  = (const float*)d_in[9];
    const float* bk  = (const float*)d_in[10];
    const float* Wv  = (const float*)d_in[11];
    const float* bv  = (const float*)d_in[12];
    const float* Wkp = (const float*)d_in[13];
    const float* bkp = (const float*)d_in[14];
    const float* Wvp = (const float*)d_in[15];
    const float* bvp = (const float*)d_in[16];
    const float* Wo  = (const float*)d_in[17];
    const float* bo  = (const float*)d_in[18];
    const float* lng = (const float*)d_in[19];
    const float* lnb = (const float*)d_in[20];
    float* out = (float*)d_out;

    xcol_kernel<<<4096*112/256, 256>>>(x);
    wpad_kernel<<<512*448/256, 256>>>(w1, w2, w3);
    conv_gemm_kernel<<<dim3(4096/128, 4), 256>>>(b1, b2, b3);
    qkv_kernel<<<dim3(4096/128, 12), 256>>>(Wq, bq, Wk, bk, Wv, bv);   // 4th: profiled
    kpvp_kernel<<<32768/64, 256>>>(Wkp, bkp, Wvp, bvp);
    scores_kernel<<<dim3(16, 16, 16), 256>>>();
    topk_kernel<<<32768/8, 256>>>();
    spout_local_kernel<<<32768/8, 256>>>(Wvp, bvp);
    outproj_kernel<<<dim3(4096/128, 4), 256>>>(Wo, bo);
    ln_kernel<<<4096, 256>>>(lng, lnb, out);
}